// round 2
// baseline (speedup 1.0000x reference)
#include <cuda_runtime.h>

#define B_  4
#define N_  16384
#define M_  4096
#define K_  16
#define R2  0.25f

// Scratch: (x, y, z, |p|^2) per point. 4*16384*16B = 1 MB.
__device__ float4 g_pts[B_ * N_];

__global__ __launch_bounds__(256) void prep_kernel(const float* __restrict__ xyz) {
    int i = blockIdx.x * blockDim.x + threadIdx.x;
    if (i < B_ * N_) {
        float x = xyz[3 * i + 0];
        float y = xyz[3 * i + 1];
        float z = xyz[3 * i + 2];
        // match jnp.sum(x**2, -1): (x*x + y*y) + z*z, no fma contraction
        float sq = __fadd_rn(__fadd_rn(__fmul_rn(x, x), __fmul_rn(y, y)), __fmul_rn(z, z));
        g_pts[i] = make_float4(x, y, z, sq);
    }
}

__device__ __forceinline__ float dist2(float4 q, float4 p) {
    float dot = __fadd_rn(__fadd_rn(__fmul_rn(q.x, p.x), __fmul_rn(q.y, p.y)),
                          __fmul_rn(q.z, p.z));
    return __fsub_rn(__fadd_rn(q.w, p.w), __fmul_rn(2.0f, dot));
}

__global__ __launch_bounds__(256) void sa_kernel(
    const float* __restrict__ feat,
    const int*   __restrict__ fps_idx,
    const float* __restrict__ W1,
    const float* __restrict__ b1,
    const float* __restrict__ W2,
    const float* __restrict__ b2,
    float*       __restrict__ out)
{
    __shared__ float W1s[6 * 32];
    __shared__ float W2s[32 * 32];
    __shared__ float b1s[32];
    __shared__ float b2s[32];

    int tid = threadIdx.x;
    for (int i = tid; i < 6 * 32; i += 256)   W1s[i] = W1[i];
    for (int i = tid; i < 32 * 32; i += 256)  W2s[i] = W2[i];
    if (tid < 32) { b1s[tid] = b1[tid]; b2s[tid] = b2[tid]; }
    __syncthreads();

    const unsigned FULL = 0xffffffffu;
    int lane = tid & 31;

    // hoist this lane's weight columns into registers (inner loops become
    // pure SHFL+FFMA, no LDS)
    float w1r[6], w2r[32];
    #pragma unroll
    for (int i = 0; i < 6; i++)  w1r[i] = W1s[i * 32 + lane];
    #pragma unroll
    for (int i = 0; i < 32; i++) w2r[i] = W2s[i * 32 + lane];
    float b1r = b1s[lane];
    float b2r = b2s[lane];

    int wg = blockIdx.x * 8 + (tid >> 5);     // global warp id = query id
    int b  = wg >> 12;                        // / M_ (4096)
    int m  = wg & (M_ - 1);

    const float4* __restrict__ pts = g_pts + (size_t)b * N_;

    int    qi = fps_idx[b * M_ + m];
    float4 q  = pts[qi];

    // ---- ball query: first K_ in-ball indices in ascending order ----
    // 4 independent 16B loads per iteration (MLP=4) before the exit check.
    int found  = 0;
    int my_idx = 0;                           // lane k (k<K_) owns neighbor k
    for (int base = 0; base < N_; base += 128) {
        float4 p0 = pts[base       + lane];
        float4 p1 = pts[base +  32 + lane];
        float4 p2 = pts[base +  64 + lane];
        float4 p3 = pts[base +  96 + lane];
        unsigned msk0 = __ballot_sync(FULL, dist2(q, p0) <= R2);
        unsigned msk1 = __ballot_sync(FULL, dist2(q, p1) <= R2);
        unsigned msk2 = __ballot_sync(FULL, dist2(q, p2) <= R2);
        unsigned msk3 = __ballot_sync(FULL, dist2(q, p3) <= R2);
        unsigned msks[4] = {msk0, msk1, msk2, msk3};
        #pragma unroll
        for (int j = 0; j < 4; j++) {
            unsigned mask = msks[j];
            while (mask && found < K_) {
                int bit = __ffs(mask) - 1;
                if (lane == found) my_idx = base + j * 32 + bit;
                mask &= mask - 1;
                found++;
            }
        }
        if (found >= K_) break;
    }
    // pad missing neighbors with the first valid one (reference semantics).
    // At least one always exists (the query point itself is in its own ball).
    int idx0 = __shfl_sync(FULL, my_idx, 0);
    if (lane >= found) my_idx = idx0;

    // ---- MLP + maxpool: lane j owns output channel j ----
    const float* __restrict__ featb = feat + (size_t)b * N_ * 3;
    float acc = -3.402823466e38f;

    #pragma unroll 1
    for (int k = 0; k < K_; k++) {
        int g = __shfl_sync(FULL, my_idx, k);
        float4 p = pts[g];                    // broadcast load
        float f0 = featb[3 * g + 0];
        float f1 = featb[3 * g + 1];
        float f2 = featb[3 * g + 2];
        float i0 = p.x - q.x, i1 = p.y - q.y, i2 = p.z - q.z;

        float h1 = b1r;
        h1 += i0 * w1r[0];
        h1 += i1 * w1r[1];
        h1 += i2 * w1r[2];
        h1 += f0 * w1r[3];
        h1 += f1 * w1r[4];
        h1 += f2 * w1r[5];
        h1 = fmaxf(h1, 0.1f * h1);            // leaky relu

        float h2 = b2r;
        #pragma unroll
        for (int i = 0; i < 32; i++) {
            float hv = __shfl_sync(FULL, h1, i);
            h2 = fmaf(hv, w2r[i], h2);
        }
        h2 = fmaxf(h2, 0.1f * h2);

        acc = fmaxf(acc, h2);
    }

    out[((size_t)(b * M_ + m)) * 32 + lane] = acc;
}

extern "C" void kernel_launch(void* const* d_in, const int* in_sizes, int n_in,
                              void* d_out, int out_size) {
    const float* xyz     = (const float*)d_in[0];
    const float* feat    = (const float*)d_in[1];
    const int*   fps_idx = (const int*)  d_in[2];
    const float* W1      = (const float*)d_in[3];
    const float* b1      = (const float*)d_in[4];
    const float* W2      = (const float*)d_in[5];
    const float* b2      = (const float*)d_in[6];
    float* out = (float*)d_out;

    prep_kernel<<<(B_ * N_ + 255) / 256, 256>>>(xyz);
    sa_kernel<<<(B_ * M_) / 8, 256>>>(feat, fps_idx, W1, b1, W2, b2, out);
    (void)in_sizes; (void)n_in; (void)out_size;
}

// round 3
// speedup vs baseline: 1.5284x; 1.5284x over previous
#include <cuda_runtime.h>

#define B_  4
#define N_  16384
#define M_  4096
#define K_  16
#define R2  0.25f
#define NQ  (B_ * M_)

// Scratch: (x, y, z, |p|^2) per point. 4*16384*16B = 1 MB.
__device__ float4 g_pts[B_ * N_];
__device__ unsigned int g_qctr;   // work-stealing queue head

__global__ __launch_bounds__(256) void prep_kernel(const float* __restrict__ xyz) {
    int i = blockIdx.x * blockDim.x + threadIdx.x;
    if (i == 0) g_qctr = 0;       // reset queue every launch (graph replay safe)
    if (i < B_ * N_) {
        float x = xyz[3 * i + 0];
        float y = xyz[3 * i + 1];
        float z = xyz[3 * i + 2];
        // match jnp.sum(x**2, -1): (x*x + y*y) + z*z, no fma contraction
        float sq = __fadd_rn(__fadd_rn(__fmul_rn(x, x), __fmul_rn(y, y)), __fmul_rn(z, z));
        g_pts[i] = make_float4(x, y, z, sq);
    }
}

// DO NOT change this arithmetic: it reproduces the reference's expanded
// |q|^2 + |p|^2 - 2 q.p form and determines boundary membership (rel_err).
__device__ __forceinline__ float dist2(float4 q, float4 p) {
    float dot = __fadd_rn(__fadd_rn(__fmul_rn(q.x, p.x), __fmul_rn(q.y, p.y)),
                          __fmul_rn(q.z, p.z));
    return __fsub_rn(__fadd_rn(q.w, p.w), __fmul_rn(2.0f, dot));
}

__global__ __launch_bounds__(256) void sa_kernel(
    const float* __restrict__ feat,
    const int*   __restrict__ fps_idx,
    const float* __restrict__ W1,
    const float* __restrict__ b1,
    const float* __restrict__ W2,
    const float* __restrict__ b2,
    float*       __restrict__ out)
{
    const unsigned FULL = 0xffffffffu;
    int tid  = threadIdx.x;
    int lane = tid & 31;

    // hoist this lane's weight columns into registers (inner loops become
    // pure SHFL+FFMA, no LDS/LDG)
    float w1r[6], w2r[32];
    #pragma unroll
    for (int i = 0; i < 6; i++)  w1r[i] = W1[i * 32 + lane];
    #pragma unroll
    for (int i = 0; i < 32; i++) w2r[i] = W2[i * 32 + lane];
    float b1r = b1[lane];
    float b2r = b2[lane];

    // persistent warp: steal one query at a time
    for (;;) {
        int qid;
        if (lane == 0) qid = (int)atomicAdd(&g_qctr, 1u);
        qid = __shfl_sync(FULL, qid, 0);
        if (qid >= NQ) break;

        int b = qid >> 12;            // / M_ (4096)
        int m = qid & (M_ - 1);

        const float4* __restrict__ pts = g_pts + (size_t)b * N_;

        int    qi = fps_idx[b * M_ + m];
        float4 q  = pts[qi];

        // ---- ball query: first K_ in-ball indices in ascending order ----
        // 8 independent 16B loads (256 points) in flight before the exit check.
        int found  = 0;
        int my_idx = 0;               // lane k (k<K_) owns neighbor k
        for (int base = 0; base < N_; base += 256) {
            unsigned msks[8];
            {
                float4 p0 = pts[base        + lane];
                float4 p1 = pts[base +  32 + lane];
                float4 p2 = pts[base +  64 + lane];
                float4 p3 = pts[base +  96 + lane];
                float4 p4 = pts[base + 128 + lane];
                float4 p5 = pts[base + 160 + lane];
                float4 p6 = pts[base + 192 + lane];
                float4 p7 = pts[base + 224 + lane];
                msks[0] = __ballot_sync(FULL, dist2(q, p0) <= R2);
                msks[1] = __ballot_sync(FULL, dist2(q, p1) <= R2);
                msks[2] = __ballot_sync(FULL, dist2(q, p2) <= R2);
                msks[3] = __ballot_sync(FULL, dist2(q, p3) <= R2);
                msks[4] = __ballot_sync(FULL, dist2(q, p4) <= R2);
                msks[5] = __ballot_sync(FULL, dist2(q, p5) <= R2);
                msks[6] = __ballot_sync(FULL, dist2(q, p6) <= R2);
                msks[7] = __ballot_sync(FULL, dist2(q, p7) <= R2);
            }
            #pragma unroll
            for (int j = 0; j < 8; j++) {
                unsigned mask = msks[j];
                while (mask && found < K_) {
                    int bit = __ffs(mask) - 1;
                    if (lane == found) my_idx = base + j * 32 + bit;
                    mask &= mask - 1;
                    found++;
                }
            }
            if (found >= K_) break;
        }
        // pad missing neighbors with the first valid one (reference semantics).
        // At least one always exists (the query point is in its own ball).
        int idx0 = __shfl_sync(FULL, my_idx, 0);
        if (lane >= found) my_idx = idx0;

        // ---- MLP + maxpool: lane j owns output channel j ----
        const float* __restrict__ featb = feat + (size_t)b * N_ * 3;
        float acc = -3.402823466e38f;

        #pragma unroll 1
        for (int k = 0; k < K_; k++) {
            int g = __shfl_sync(FULL, my_idx, k);
            float4 p = pts[g];                    // broadcast load (L1/L2 hit)
            float f0 = featb[3 * g + 0];
            float f1 = featb[3 * g + 1];
            float f2 = featb[3 * g + 2];
            float i0 = p.x - q.x, i1 = p.y - q.y, i2 = p.z - q.z;

            float h1 = b1r;
            h1 += i0 * w1r[0];
            h1 += i1 * w1r[1];
            h1 += i2 * w1r[2];
            h1 += f0 * w1r[3];
            h1 += f1 * w1r[4];
            h1 += f2 * w1r[5];
            h1 = fmaxf(h1, 0.1f * h1);            // leaky relu

            float h2 = b2r;
            #pragma unroll
            for (int i = 0; i < 32; i++) {
                float hv = __shfl_sync(FULL, h1, i);
                h2 = fmaf(hv, w2r[i], h2);
            }
            h2 = fmaxf(h2, 0.1f * h2);

            acc = fmaxf(acc, h2);
        }

        out[((size_t)qid) * 32 + lane] = acc;
    }
}

extern "C" void kernel_launch(void* const* d_in, const int* in_sizes, int n_in,
                              void* d_out, int out_size) {
    const float* xyz     = (const float*)d_in[0];
    const float* feat    = (const float*)d_in[1];
    const int*   fps_idx = (const int*)  d_in[2];
    const float* W1      = (const float*)d_in[3];
    const float* b1      = (const float*)d_in[4];
    const float* W2      = (const float*)d_in[5];
    const float* b2      = (const float*)d_in[6];
    float* out = (float*)d_out;

    prep_kernel<<<(B_ * N_ + 255) / 256, 256>>>(xyz);
    // persistent kernel: ~4 CTAs/SM target; excess CTAs drain the queue and exit
    sa_kernel<<<592, 256>>>(feat, fps_idx, W1, b1, W2, b2, out);
    (void)in_sizes; (void)n_in; (void)out_size;
}